// round 12
// baseline (speedup 1.0000x reference)
#include <cuda_runtime.h>
#include <cuda_fp16.h>
#include <math.h>
#include <stdint.h>

#define B_ 1024
#define N_ 64
#define E_ 1024
#define D_ 512
#define M_ (B_*N_)   // 65536 rows

// -------- scratch (device globals; no allocation allowed) --------
__device__ __half g_nk_h [B_*D_];
__device__ __half g_kWh  [E_*D_];
__device__ __half g_vWh  [E_*D_];
__device__ __half g_qWTh [E_*E_];
__device__ float  g_k    [B_*E_];
__device__ __half g_k_h  [B_*E_];
__device__ __half g_v_h  [B_*E_];
__device__ float  g_w    [B_*E_];
__device__ float  g_gw   [B_*E_];
__device__ float  g_vo   [B_*E_];
__device__ float  g_Sg   [B_];
__device__ float  g_Sb   [B_];
__device__ __half g_Bh   [(size_t)E_*E_];

// ================= PTX helpers (compute_103-safe) ==========
__device__ __forceinline__ uint32_t smem_u32(const void* p) {
    uint32_t a;
    asm("{ .reg .u64 t; cvta.to.shared.u64 t, %1; cvt.u32.u64 %0, t; }" : "=r"(a) : "l"(p));
    return a;
}
__device__ __forceinline__ void cp16(uint32_t dst, const void* src) {
    asm volatile("cp.async.cg.shared.global [%0], [%1], 16;" :: "r"(dst), "l"(src));
}
#define CP_COMMIT() asm volatile("cp.async.commit_group;" ::: "memory")
#define CP_WAIT2()  asm volatile("cp.async.wait_group 2;" ::: "memory")
#define CP_WAIT1()  asm volatile("cp.async.wait_group 1;" ::: "memory")

__device__ __forceinline__ void ldm4(uint32_t& r0, uint32_t& r1, uint32_t& r2,
                                     uint32_t& r3, uint32_t a) {
    asm volatile("ldmatrix.sync.aligned.m8n8.x4.shared.b16 {%0,%1,%2,%3}, [%4];"
                 : "=r"(r0), "=r"(r1), "=r"(r2), "=r"(r3) : "r"(a));
}
__device__ __forceinline__ void mma16816(float* c, const uint32_t* a,
                                         uint32_t b0, uint32_t b1) {
    asm volatile("mma.sync.aligned.m16n8k16.row.col.f32.f16.f16.f32 "
                 "{%0,%1,%2,%3},{%4,%5,%6,%7},{%8,%9},{%0,%1,%2,%3};"
                 : "+f"(c[0]), "+f"(c[1]), "+f"(c[2]), "+f"(c[3])
                 : "r"(a[0]), "r"(a[1]), "r"(a[2]), "r"(a[3]), "r"(b0), "r"(b1));
}

// ================= merged weight converts =================
// blocks [0,1024): oW->Bh (1M elems); [1024,1536): kW->kWh; [1536,2048): vW->vWh
__global__ void cvt3_kernel(const float* __restrict__ oW,
                            const float* __restrict__ kW,
                            const float* __restrict__ vW,
                            __half* __restrict__ bh,
                            __half* __restrict__ kwh,
                            __half* __restrict__ vwh) {
    int blk = blockIdx.x;
    const float* src;
    __half* dst;
    size_t base;
    if (blk < 1024) { src = oW; dst = bh; base = (size_t)blk * 1024; }
    else if (blk < 1536) { src = kW; dst = kwh; base = (size_t)(blk - 1024) * 1024; }
    else { src = vW; dst = vwh; base = (size_t)(blk - 1536) * 1024; }
    size_t i = base + threadIdx.x * 4;
    float4 v = *(const float4*)(src + i);
    __half2 a = __floats2half2_rn(v.x, v.y);
    __half2 b = __floats2half2_rn(v.z, v.w);
    uint2 p;
    p.x = *(uint32_t*)&a; p.y = *(uint32_t*)&b;
    *(uint2*)(dst + i) = p;
}

__global__ void transpose_cvt_kernel(const float* __restrict__ in, __half* __restrict__ out) {
    __shared__ float t[32][33];
    int tx = threadIdx.x, ty = threadIdx.y;
    int bx = blockIdx.x * 32, by = blockIdx.y * 32;
    #pragma unroll
    for (int i = 0; i < 32; i += 8)
        t[ty + i][tx] = in[(size_t)(by + ty + i) * E_ + bx + tx];
    __syncthreads();
    #pragma unroll
    for (int i = 0; i < 32; i += 8)
        out[(size_t)(bx + ty + i) * E_ + by + tx] = __float2half(t[tx][ty + i]);
}

// -------- LayerNorm of context -> fp16 nk --------
__global__ void ln_ctx_kernel(const float* __restrict__ ctx,
                              const float* __restrict__ gam,
                              const float* __restrict__ bet) {
    int b = blockIdx.x, tid = threadIdx.x;
    const float* x = ctx + (size_t)b * D_;
    float v0 = x[tid], v1 = x[tid + 256];
    __shared__ float r1[256], r2[256];
    r1[tid] = v0 + v1;
    r2[tid] = v0 * v0 + v1 * v1;
    __syncthreads();
    for (int o = 128; o > 0; o >>= 1) {
        if (tid < o) { r1[tid] += r1[tid + o]; r2[tid] += r2[tid + o]; }
        __syncthreads();
    }
    float mu = r1[0] * (1.0f / D_);
    float var = r2[0] * (1.0f / D_) - mu * mu;
    float rstd = rsqrtf(var + 1e-5f);
    g_nk_h[(size_t)b * D_ + tid]       = __float2half((v0 - mu) * rstd * gam[tid]       + bet[tid]);
    g_nk_h[(size_t)b * D_ + tid + 256] = __float2half((v1 - mu) * rstd * gam[tid + 256] + bet[tid + 256]);
}

// ================= aux fp16 GEMM (dual via blockIdx.z) =================
struct GemmArgs {
    const __half* A;
    const __half* Bm;
    const float*  bias;
    float*        Cf;
    __half*       Ch;
    const float*  colmul;
    float*        C2f;
};

#define AG_AROWB 80
#define AG_ASZ   (128*AG_AROWB)
#define AG_STG   (2*AG_ASZ)
#define AG_STAGES 3

__device__ __forceinline__ void ag_issue(uint32_t sbase, int stage, int it,
                                         int bm, int bn, int tid,
                                         const __half* A, const __half* Bm, int K) {
    int kk = it << 5;
    uint32_t ab = sbase + stage * AG_STG;
    uint32_t bb = ab + AG_ASZ;
    #pragma unroll
    for (int j = 0; j < 2; j++) {
        int id = tid + j * 256;
        int r = id >> 2, c = id & 3;
        cp16(ab + r * AG_AROWB + c * 16, A  + (size_t)(bm + r) * K + kk + c * 8);
        cp16(bb + r * AG_AROWB + c * 16, Bm + (size_t)(bn + r) * K + kk + c * 8);
    }
}

__global__ void __launch_bounds__(256, 1) gemm_h_dual(GemmArgs g0, GemmArgs g1, int K) {
    extern __shared__ char smem[];
    uint32_t sbase = smem_u32(smem);
    const GemmArgs g = (blockIdx.z == 0) ? g0 : g1;
    const __half* A = g.A;
    const __half* Bm = g.Bm;
    int tid = threadIdx.x, wid = tid >> 5, lane = tid & 31;
    int bm = blockIdx.y * 128, bn = blockIdx.x * 128;
    int wm = wid & 1, wn = wid >> 1;
    int iters = K >> 5;

    float acc[4][4][4] = {};

    ag_issue(sbase, 0, 0, bm, bn, tid, A, Bm, K); CP_COMMIT();
    ag_issue(sbase, 1, 1, bm, bn, tid, A, Bm, K); CP_COMMIT();

    int l15 = lane & 15, l16 = lane >> 4;

    for (int i = 0; i < iters; i++) {
        CP_WAIT1();
        __syncthreads();
        int s = i % 3;
        uint32_t ab = sbase + s * AG_STG;
        uint32_t bb = ab + AG_ASZ;
        #pragma unroll
        for (int ks = 0; ks < 2; ks++) {
            int kc = ks * 2;
            uint32_t aaddr = ab + (wm * 64 + l15) * AG_AROWB + (kc + l16) * 16;
            uint32_t baddr = bb + (wn * 32 + l15) * AG_AROWB + (kc + l16) * 16;
            uint32_t ar[4][4], br[2][4];
            #pragma unroll
            for (int mi = 0; mi < 4; mi++)
                ldm4(ar[mi][0], ar[mi][1], ar[mi][2], ar[mi][3],
                     aaddr + mi * 16 * AG_AROWB);
            #pragma unroll
            for (int nb = 0; nb < 2; nb++)
                ldm4(br[nb][0], br[nb][1], br[nb][2], br[nb][3],
                     baddr + nb * 16 * AG_AROWB);
            #pragma unroll
            for (int mi = 0; mi < 4; mi++) {
                #pragma unroll
                for (int nb = 0; nb < 2; nb++) {
                    mma16816(acc[mi][2 * nb + 0], ar[mi], br[nb][0], br[nb][2]);
                    mma16816(acc[mi][2 * nb + 1], ar[mi], br[nb][1], br[nb][3]);
                }
            }
        }
        if (i + 2 < iters)
            ag_issue(sbase, (i + 2) % 3, i + 2, bm, bn, tid, A, Bm, K);
        CP_COMMIT();
    }

    int lr = lane >> 2, lc = (lane & 3) * 2;
    #pragma unroll
    for (int mi = 0; mi < 4; mi++) {
        int row0 = bm + wm * 64 + mi * 16 + lr;
        int row1 = row0 + 8;
        #pragma unroll
        for (int ni = 0; ni < 4; ni++) {
            int col = bn + wn * 32 + ni * 8 + lc;
            float b0 = g.bias ? g.bias[col] : 0.0f;
            float b1 = g.bias ? g.bias[col + 1] : 0.0f;
            float v00 = acc[mi][ni][0] + b0, v01 = acc[mi][ni][1] + b1;
            float v10 = acc[mi][ni][2] + b0, v11 = acc[mi][ni][3] + b1;
            if (g.Cf) {
                *(float2*)(g.Cf + (size_t)row0 * 1024 + col) = make_float2(v00, v01);
                *(float2*)(g.Cf + (size_t)row1 * 1024 + col) = make_float2(v10, v11);
            }
            if (g.Ch) {
                __half2 h0 = __floats2half2_rn(v00, v01);
                __half2 h1 = __floats2half2_rn(v10, v11);
                *(__half2*)(g.Ch + (size_t)row0 * 1024 + col) = h0;
                *(__half2*)(g.Ch + (size_t)row1 * 1024 + col) = h1;
            }
            if (g.C2f) {
                float c0 = g.colmul[col], c1 = g.colmul[col + 1];
                *(float2*)(g.C2f + (size_t)row0 * 1024 + col) = make_float2(c0 * v00, c1 * v01);
                *(float2*)(g.C2f + (size_t)row1 * 1024 + col) = make_float2(c0 * v10, c1 * v11);
            }
        }
    }
}

// ================= scalars =================
__global__ void scalars_kernel(const float* __restrict__ qb,
                               const float* __restrict__ lnq_b) {
    int warp = threadIdx.x >> 5, lane = threadIdx.x & 31;
    int b = blockIdx.x * 8 + warp;
    const float* gw = g_gw + (size_t)b * E_;
    const float* w  = g_w  + (size_t)b * E_;
    const float* k  = g_k  + (size_t)b * E_;
    float sg = 0.f, sb = 0.f, cb = 0.f;
    for (int i = lane; i < E_; i += 32) {
        sg += gw[i];
        sb += lnq_b[i] * w[i];
        cb += qb[i] * k[i];
    }
    #pragma unroll
    for (int o = 16; o > 0; o >>= 1) {
        sg += __shfl_xor_sync(0xffffffffu, sg, o);
        sb += __shfl_xor_sync(0xffffffffu, sb, o);
        cb += __shfl_xor_sync(0xffffffffu, cb, o);
    }
    if (lane == 0) { g_Sg[b] = sg; g_Sb[b] = sb + cb; }
}

// ================= main GEMM (fp32 A in, inline attn stats) =================
// out = re @ oW^T + attn*vo + ob.  CTA 128x256, 256 threads, warp 64x64, BK=32.
// A: LDG fp32 + in-reg convert + STS fp16 (double-buffered); stats (s1,s2,sd)
// accumulated from the fp32 A values; attn computed in-kernel.
// B: 4-stage cp.async of g_Bh.
#define V2_AROWB 80
#define V2_ABUF  (128*V2_AROWB)             // 10240
#define V2_BOFF  (2*V2_ABUF)                // 20480
#define V2_BSTG  (256*V2_AROWB)             // 20480
#define V2_ATTN  (V2_BOFF + 4*V2_BSTG)      // 102400
#define V2_SMEM  (V2_ATTN + 512)            // 102912
#define V2_ITERS 32

__device__ __forceinline__ void v2_issueB(uint32_t sbase, int stage, int it,
                                          int bn, int tid) {
    int kk = it << 5;
    uint32_t bb = sbase + V2_BOFF + stage * V2_BSTG;
    #pragma unroll
    for (int j = 0; j < 4; j++) {
        int id = tid + j * 256;
        int r = id >> 2, c = id & 3;
        cp16(bb + r * V2_AROWB + c * 16,
             g_Bh + (size_t)(bn + r) * E_ + kk + c * 8);
    }
}

__device__ __forceinline__ void v2_ldgA(const float* __restrict__ re, int bm,
                                        int row, int half, int it, float4* q,
                                        float& s1, float& s2, float& sd) {
    int kk = it << 5;
    const float4* src = (const float4*)(re + (size_t)(bm + row) * E_ + kk + half * 16);
    const float4* gsr = (const float4*)(g_gw + (size_t)((bm + row) >> 6) * E_ + kk + half * 16);
    #pragma unroll
    for (int j = 0; j < 4; j++) {
        float4 t = src[j];
        float4 g = gsr[j];
        q[j] = t;
        s1 += t.x + t.y + t.z + t.w;
        s2 += t.x * t.x + t.y * t.y + t.z * t.z + t.w * t.w;
        sd += t.x * g.x + t.y * g.y + t.z * g.z + t.w * g.w;
    }
}

__device__ __forceinline__ void v2_stsA(char* smem, int buf, int row, int half,
                                        const float4* q) {
    uint4 u0, u1;
    __half2 h;
    h = __floats2half2_rn(q[0].x, q[0].y); u0.x = *(uint32_t*)&h;
    h = __floats2half2_rn(q[0].z, q[0].w); u0.y = *(uint32_t*)&h;
    h = __floats2half2_rn(q[1].x, q[1].y); u0.z = *(uint32_t*)&h;
    h = __floats2half2_rn(q[1].z, q[1].w); u0.w = *(uint32_t*)&h;
    h = __floats2half2_rn(q[2].x, q[2].y); u1.x = *(uint32_t*)&h;
    h = __floats2half2_rn(q[2].z, q[2].w); u1.y = *(uint32_t*)&h;
    h = __floats2half2_rn(q[3].x, q[3].y); u1.z = *(uint32_t*)&h;
    h = __floats2half2_rn(q[3].z, q[3].w); u1.w = *(uint32_t*)&h;
    char* p = smem + buf * V2_ABUF + row * V2_AROWB + half * 32;
    *(uint4*)p = u0;
    *(uint4*)(p + 16) = u1;
}

__global__ void __launch_bounds__(256, 1) main_gemm_v2(const float* __restrict__ re,
                                                       const float* __restrict__ ob,
                                                       float* __restrict__ out) {
    extern __shared__ char smem[];
    uint32_t sbase = smem_u32(smem);
    int tid = threadIdx.x, wid = tid >> 5, lane = tid & 31;
    int bm = blockIdx.y * 128, bn = blockIdx.x * 256;
    int wm = wid & 1, wn = wid >> 1;
    int arow = tid >> 1, ahalf = tid & 1;

    float acc[4][8][4] = {};
    float s1 = 0.f, s2 = 0.f, sd = 0.f;
    float4 q[4];

    // prologue: A iters 0,1; B stages 0..2
    v2_ldgA(re, bm, arow, ahalf, 0, q, s1, s2, sd);
    v2_stsA(smem, 0, arow, ahalf, q);
    v2_ldgA(re, bm, arow, ahalf, 1, q, s1, s2, sd);
    v2_issueB(sbase, 0, 0, bn, tid); CP_COMMIT();
    v2_issueB(sbase, 1, 1, bn, tid); CP_COMMIT();
    v2_issueB(sbase, 2, 2, bn, tid); CP_COMMIT();

    int l15 = lane & 15, l16 = lane >> 4;

    for (int i = 0; i < V2_ITERS; i++) {
        CP_WAIT2();
        __syncthreads();
        // stage iter i+1's A data (regs q) into buf (i+1)&1
        v2_stsA(smem, (i + 1) & 1, arow, ahalf, q);
        uint32_t ab = sbase + (i & 1) * V2_ABUF;
        uint32_t bb = sbase + V2_BOFF + (i & 3) * V2_BSTG;
        #pragma unroll
        for (int ks = 0; ks < 2; ks++) {
            int kc = ks * 2;
            uint32_t aaddr = ab + (wm * 64 + l15) * V2_AROWB + (kc + l16) * 16;
            uint32_t baddr = bb + (wn * 64 + l15) * V2_AROWB + (kc + l16) * 16;
            uint32_t ar[4][4], br[4][4];
            #pragma unroll
            for (int mi = 0; mi < 4; mi++)
                ldm4(ar[mi][0], ar[mi][1], ar[mi][2], ar[mi][3],
                     aaddr + mi * 16 * V2_AROWB);
            #pragma unroll
            for (int nb = 0; nb < 4; nb++)
                ldm4(br[nb][0], br[nb][1], br[nb][2], br[nb][3],
                     baddr + nb * 16 * V2_AROWB);
            #pragma unroll
            for (int mi = 0; mi < 4; mi++) {
                #pragma unroll
                for (int nb = 0; nb < 4; nb++) {
                    mma16816(acc[mi][2 * nb + 0], ar[mi], br[nb][0], br[nb][2]);
                    mma16816(acc[mi][2 * nb + 1], ar[mi], br[nb][1], br[nb][3]);
                }
            }
        }
        if (i + 2 < V2_ITERS)
            v2_ldgA(re, bm, arow, ahalf, i + 2, q, s1, s2, sd);
        if (i + 3 < V2_ITERS)
            v2_issueB(sbase, (i + 3) & 3, i + 3, bn, tid);
        CP_COMMIT();
    }

    // finalize attn for this CTA's 128 rows (each row owned by 2 threads)
    s1 += __shfl_xor_sync(0xffffffffu, s1, 1);
    s2 += __shfl_xor_sync(0xffffffffu, s2, 1);
    sd += __shfl_xor_sync(0xffffffffu, sd, 1);
    float* attn_s = (float*)(smem + V2_ATTN);
    if (ahalf == 0) {
        int b = (bm + arow) >> 6;
        float mu = s1 * (1.0f / E_);
        float var = s2 * (1.0f / E_) - mu * mu;
        float rstd = rsqrtf(var + 1e-5f);
        float score = 0.03125f * (rstd * (sd - mu * g_Sg[b]) + g_Sb[b]);
        attn_s[arow] = tanhf(score);
    }
    __syncthreads();

    int lr = lane >> 2, lc = (lane & 3) * 2;
    #pragma unroll
    for (int mi = 0; mi < 4; mi++) {
        int lrow0 = wm * 64 + mi * 16 + lr;
        int row0 = bm + lrow0;
        int row1 = row0 + 8;
        float am0 = attn_s[lrow0], am1 = attn_s[lrow0 + 8];
        const float* vo0 = g_vo + (size_t)(row0 >> 6) * E_;
        const float* vo1 = g_vo + (size_t)(row1 >> 6) * E_;
        float* o0 = out + (size_t)row0 * E_;
        float* o1 = out + (size_t)row1 * E_;
        #pragma unroll
        for (int ni = 0; ni < 8; ni++) {
            int col = bn + wn * 64 + ni * 8 + lc;
            float2 r0, r1;
            r0.x = acc[mi][ni][0] + am0 * vo0[col]     + ob[col];
            r0.y = acc[mi][ni][1] + am0 * vo0[col + 1] + ob[col + 1];
            r1.x = acc[mi][ni][2] + am1 * vo1[col]     + ob[col];
            r1.y = acc[mi][ni][3] + am1 * vo1[col + 1] + ob[col + 1];
            *(float2*)(o0 + col) = r0;
            *(float2*)(o1 + col) = r1;
        }
    }
}

extern "C" void kernel_launch(void* const* d_in, const int* in_sizes, int n_in,
                              void* d_out, int out_size) {
    const float* re    = (const float*)d_in[0];
    const float* ctx   = (const float*)d_in[1];
    const float* qW    = (const float*)d_in[2];
    const float* qb    = (const float*)d_in[3];
    const float* kW    = (const float*)d_in[4];
    const float* kb    = (const float*)d_in[5];
    const float* vW    = (const float*)d_in[6];
    const float* vb    = (const float*)d_in[7];
    const float* oW    = (const float*)d_in[8];
    const float* ob    = (const float*)d_in[9];
    const float* lnq_g = (const float*)d_in[10];
    const float* lnq_b = (const float*)d_in[11];
    const float* lnk_g = (const float*)d_in[12];
    const float* lnk_b = (const float*)d_in[13];
    float* out = (float*)d_out;

    void *p_nkh, *p_kwh, *p_vwh, *p_qwth, *p_k, *p_kh, *p_vh, *p_w, *p_gw, *p_vo, *p_bh;
    cudaGetSymbolAddress(&p_nkh,  g_nk_h);
    cudaGetSymbolAddress(&p_kwh,  g_kWh);
    cudaGetSymbolAddress(&p_vwh,  g_vWh);
    cudaGetSymbolAddress(&p_qwth, g_qWTh);
    cudaGetSymbolAddress(&p_k,    g_k);
    cudaGetSymbolAddress(&p_kh,   g_k_h);
    cudaGetSymbolAddress(&p_vh,   g_v_h);
    cudaGetSymbolAddress(&p_w,    g_w);
    cudaGetSymbolAddress(&p_gw,   g_gw);
    cudaGetSymbolAddress(&p_vo,   g_vo);
    cudaGetSymbolAddress(&p_bh,   g_Bh);

    const int ag_smem = AG_STAGES * AG_STG;   // 61440
    cudaFuncSetAttribute(gemm_h_dual, cudaFuncAttributeMaxDynamicSharedMemorySize, ag_smem);
    cudaFuncSetAttribute(main_gemm_v2, cudaFuncAttributeMaxDynamicSharedMemorySize, V2_SMEM);

    // 0. weight converts (one kernel) + qW transpose
    cvt3_kernel<<<2048, 256>>>(oW, kW, vW, (__half*)p_bh, (__half*)p_kwh, (__half*)p_vwh);
    transpose_cvt_kernel<<<dim3(32, 32), dim3(32, 8)>>>(qW, (__half*)p_qwth);
    // 1. nk = LN(context) -> fp16
    ln_ctx_kernel<<<B_, 256>>>(ctx, lnk_g, lnk_b);
    // 2. k = nk@kW^T+kb  ||  v = nk@vW^T+vb
    {
        GemmArgs gk = { (__half*)p_nkh, (__half*)p_kwh, kb, (float*)p_k, (__half*)p_kh, nullptr, nullptr };
        GemmArgs gv = { (__half*)p_nkh, (__half*)p_vwh, vb, nullptr, (__half*)p_vh, nullptr, nullptr };
        gemm_h_dual<<<dim3(8, 8, 2), 256, ag_smem>>>(gk, gv, D_);
    }
    // 3. w = k@qW (+gw)  ||  vo = v@oW^T
    {
        GemmArgs gw_ = { (__half*)p_kh, (__half*)p_qwth, nullptr, (float*)p_w, nullptr, lnq_g, (float*)p_gw };
        GemmArgs gvo = { (__half*)p_vh, (__half*)p_bh, nullptr, (float*)p_vo, nullptr, nullptr, nullptr };
        gemm_h_dual<<<dim3(8, 8, 2), 256, ag_smem>>>(gw_, gvo, E_);
    }
    // 4. per-batch scalars
    scalars_kernel<<<B_ / 8, 256>>>(qb, lnq_b);
    // 5. out = re @ oW^T + attn*vo + ob (attn computed inline)
    main_gemm_v2<<<dim3(4, 512), 256, V2_SMEM>>>(re, ob, out);
}

// round 13
// speedup vs baseline: 1.3109x; 1.3109x over previous
#include <cuda_runtime.h>
#include <cuda_fp16.h>
#include <math.h>
#include <stdint.h>

#define B_ 1024
#define N_ 64
#define E_ 1024
#define D_ 512
#define M_ (B_*N_)   // 65536 rows

// -------- scratch (device globals; no allocation allowed) --------
__device__ __half g_nk_h [B_*D_];
__device__ __half g_kWh  [E_*D_];
__device__ __half g_vWh  [E_*D_];
__device__ __half g_qWTh [E_*E_];
__device__ float  g_k    [B_*E_];
__device__ __half g_k_h  [B_*E_];
__device__ __half g_v_h  [B_*E_];
__device__ float  g_w    [B_*E_];
__device__ float  g_gw   [B_*E_];
__device__ float  g_vo   [B_*E_];
__device__ float  g_Sg   [B_];
__device__ float  g_Sb   [B_];
__device__ float  g_attn [M_];
__device__ __half g_Ah   [(size_t)M_*E_];
__device__ __half g_Bh   [(size_t)E_*E_];

// ================= PTX helpers (compute_103-safe) ==========
__device__ __forceinline__ uint32_t smem_u32(const void* p) {
    uint32_t a;
    asm("{ .reg .u64 t; cvta.to.shared.u64 t, %1; cvt.u32.u64 %0, t; }" : "=r"(a) : "l"(p));
    return a;
}
__device__ __forceinline__ void cp16(uint32_t dst, const void* src) {
    asm volatile("cp.async.cg.shared.global [%0], [%1], 16;" :: "r"(dst), "l"(src));
}
#define CP_COMMIT() asm volatile("cp.async.commit_group;" ::: "memory")
#define CP_WAIT2()  asm volatile("cp.async.wait_group 2;" ::: "memory")
#define CP_WAIT1()  asm volatile("cp.async.wait_group 1;" ::: "memory")

__device__ __forceinline__ void ldm4(uint32_t& r0, uint32_t& r1, uint32_t& r2,
                                     uint32_t& r3, uint32_t a) {
    asm volatile("ldmatrix.sync.aligned.m8n8.x4.shared.b16 {%0,%1,%2,%3}, [%4];"
                 : "=r"(r0), "=r"(r1), "=r"(r2), "=r"(r3) : "r"(a));
}
__device__ __forceinline__ void mma16816(float* c, const uint32_t* a,
                                         uint32_t b0, uint32_t b1) {
    asm volatile("mma.sync.aligned.m16n8k16.row.col.f32.f16.f16.f32 "
                 "{%0,%1,%2,%3},{%4,%5,%6,%7},{%8,%9},{%0,%1,%2,%3};"
                 : "+f"(c[0]), "+f"(c[1]), "+f"(c[2]), "+f"(c[3])
                 : "r"(a[0]), "r"(a[1]), "r"(a[2]), "r"(a[3]), "r"(b0), "r"(b1));
}

// ================= merged weight converts =================
// blocks [0,1024): oW->Bh; [1024,1536): kW->kWh; [1536,2048): vW->vWh
__global__ void cvt3_kernel(const float* __restrict__ oW,
                            const float* __restrict__ kW,
                            const float* __restrict__ vW,
                            __half* __restrict__ bh,
                            __half* __restrict__ kwh,
                            __half* __restrict__ vwh) {
    int blk = blockIdx.x;
    const float* src;
    __half* dst;
    size_t base;
    if (blk < 1024) { src = oW; dst = bh; base = (size_t)blk * 1024; }
    else if (blk < 1536) { src = kW; dst = kwh; base = (size_t)(blk - 1024) * 1024; }
    else { src = vW; dst = vwh; base = (size_t)(blk - 1536) * 1024; }
    size_t i = base + threadIdx.x * 4;
    float4 v = *(const float4*)(src + i);
    __half2 a = __floats2half2_rn(v.x, v.y);
    __half2 b = __floats2half2_rn(v.z, v.w);
    uint2 p;
    p.x = *(uint32_t*)&a; p.y = *(uint32_t*)&b;
    *(uint2*)(dst + i) = p;
}

__global__ void transpose_cvt_kernel(const float* __restrict__ in, __half* __restrict__ out) {
    __shared__ float t[32][33];
    int tx = threadIdx.x, ty = threadIdx.y;
    int bx = blockIdx.x * 32, by = blockIdx.y * 32;
    #pragma unroll
    for (int i = 0; i < 32; i += 8)
        t[ty + i][tx] = in[(size_t)(by + ty + i) * E_ + bx + tx];
    __syncthreads();
    #pragma unroll
    for (int i = 0; i < 32; i += 8)
        out[(size_t)(bx + ty + i) * E_ + by + tx] = __float2half(t[tx][ty + i]);
}

// -------- LayerNorm of context -> fp16 nk --------
__global__ void ln_ctx_kernel(const float* __restrict__ ctx,
                              const float* __restrict__ gam,
                              const float* __restrict__ bet) {
    int b = blockIdx.x, tid = threadIdx.x;
    const float* x = ctx + (size_t)b * D_;
    float v0 = x[tid], v1 = x[tid + 256];
    __shared__ float r1[256], r2[256];
    r1[tid] = v0 + v1;
    r2[tid] = v0 * v0 + v1 * v1;
    __syncthreads();
    for (int o = 128; o > 0; o >>= 1) {
        if (tid < o) { r1[tid] += r1[tid + o]; r2[tid] += r2[tid + o]; }
        __syncthreads();
    }
    float mu = r1[0] * (1.0f / D_);
    float var = r2[0] * (1.0f / D_) - mu * mu;
    float rstd = rsqrtf(var + 1e-5f);
    g_nk_h[(size_t)b * D_ + tid]       = __float2half((v0 - mu) * rstd * gam[tid]       + bet[tid]);
    g_nk_h[(size_t)b * D_ + tid + 256] = __float2half((v1 - mu) * rstd * gam[tid + 256] + bet[tid + 256]);
}

// ================= aux fp16 GEMM (dual via blockIdx.z) =================
struct GemmArgs {
    const __half* A;
    const __half* Bm;
    const float*  bias;
    float*        Cf;
    __half*       Ch;
    const float*  colmul;
    float*        C2f;
};

#define AG_AROWB 80
#define AG_ASZ   (128*AG_AROWB)
#define AG_STG   (2*AG_ASZ)
#define AG_STAGES 3

__device__ __forceinline__ void ag_issue(uint32_t sbase, int stage, int it,
                                         int bm, int bn, int tid,
                                         const __half* A, const __half* Bm, int K) {
    int kk = it << 5;
    uint32_t ab = sbase + stage * AG_STG;
    uint32_t bb = ab + AG_ASZ;
    #pragma unroll
    for (int j = 0; j < 2; j++) {
        int id = tid + j * 256;
        int r = id >> 2, c = id & 3;
        cp16(ab + r * AG_AROWB + c * 16, A  + (size_t)(bm + r) * K + kk + c * 8);
        cp16(bb + r * AG_AROWB + c * 16, Bm + (size_t)(bn + r) * K + kk + c * 8);
    }
}

__global__ void __launch_bounds__(256, 1) gemm_h_dual(GemmArgs g0, GemmArgs g1, int K) {
    extern __shared__ char smem[];
    uint32_t sbase = smem_u32(smem);
    const GemmArgs g = (blockIdx.z == 0) ? g0 : g1;
    const __half* A = g.A;
    const __half* Bm = g.Bm;
    int tid = threadIdx.x, wid = tid >> 5, lane = tid & 31;
    int bm = blockIdx.y * 128, bn = blockIdx.x * 128;
    int wm = wid & 1, wn = wid >> 1;
    int iters = K >> 5;

    float acc[4][4][4] = {};

    ag_issue(sbase, 0, 0, bm, bn, tid, A, Bm, K); CP_COMMIT();
    ag_issue(sbase, 1, 1, bm, bn, tid, A, Bm, K); CP_COMMIT();

    int l15 = lane & 15, l16 = lane >> 4;

    for (int i = 0; i < iters; i++) {
        CP_WAIT1();
        __syncthreads();
        int s = i % 3;
        uint32_t ab = sbase + s * AG_STG;
        uint32_t bb = ab + AG_ASZ;
        #pragma unroll
        for (int ks = 0; ks < 2; ks++) {
            int kc = ks * 2;
            uint32_t aaddr = ab + (wm * 64 + l15) * AG_AROWB + (kc + l16) * 16;
            uint32_t baddr = bb + (wn * 32 + l15) * AG_AROWB + (kc + l16) * 16;
            uint32_t ar[4][4], br[2][4];
            #pragma unroll
            for (int mi = 0; mi < 4; mi++)
                ldm4(ar[mi][0], ar[mi][1], ar[mi][2], ar[mi][3],
                     aaddr + mi * 16 * AG_AROWB);
            #pragma unroll
            for (int nb = 0; nb < 2; nb++)
                ldm4(br[nb][0], br[nb][1], br[nb][2], br[nb][3],
                     baddr + nb * 16 * AG_AROWB);
            #pragma unroll
            for (int mi = 0; mi < 4; mi++) {
                #pragma unroll
                for (int nb = 0; nb < 2; nb++) {
                    mma16816(acc[mi][2 * nb + 0], ar[mi], br[nb][0], br[nb][2]);
                    mma16816(acc[mi][2 * nb + 1], ar[mi], br[nb][1], br[nb][3]);
                }
            }
        }
        if (i + 2 < iters)
            ag_issue(sbase, (i + 2) % 3, i + 2, bm, bn, tid, A, Bm, K);
        CP_COMMIT();
    }

    int lr = lane >> 2, lc = (lane & 3) * 2;
    #pragma unroll
    for (int mi = 0; mi < 4; mi++) {
        int row0 = bm + wm * 64 + mi * 16 + lr;
        int row1 = row0 + 8;
        #pragma unroll
        for (int ni = 0; ni < 4; ni++) {
            int col = bn + wn * 32 + ni * 8 + lc;
            float b0 = g.bias ? g.bias[col] : 0.0f;
            float b1 = g.bias ? g.bias[col + 1] : 0.0f;
            float v00 = acc[mi][ni][0] + b0, v01 = acc[mi][ni][1] + b1;
            float v10 = acc[mi][ni][2] + b0, v11 = acc[mi][ni][3] + b1;
            if (g.Cf) {
                *(float2*)(g.Cf + (size_t)row0 * 1024 + col) = make_float2(v00, v01);
                *(float2*)(g.Cf + (size_t)row1 * 1024 + col) = make_float2(v10, v11);
            }
            if (g.Ch) {
                __half2 h0 = __floats2half2_rn(v00, v01);
                __half2 h1 = __floats2half2_rn(v10, v11);
                *(__half2*)(g.Ch + (size_t)row0 * 1024 + col) = h0;
                *(__half2*)(g.Ch + (size_t)row1 * 1024 + col) = h1;
            }
            if (g.C2f) {
                float c0 = g.colmul[col], c1 = g.colmul[col + 1];
                *(float2*)(g.C2f + (size_t)row0 * 1024 + col) = make_float2(c0 * v00, c1 * v01);
                *(float2*)(g.C2f + (size_t)row1 * 1024 + col) = make_float2(c0 * v10, c1 * v11);
            }
        }
    }
}

// ================= scalars =================
__global__ void scalars_kernel(const float* __restrict__ qb,
                               const float* __restrict__ lnq_b) {
    int warp = threadIdx.x >> 5, lane = threadIdx.x & 31;
    int b = blockIdx.x * 8 + warp;
    const float* gw = g_gw + (size_t)b * E_;
    const float* w  = g_w  + (size_t)b * E_;
    const float* k  = g_k  + (size_t)b * E_;
    float sg = 0.f, sb = 0.f, cb = 0.f;
    for (int i = lane; i < E_; i += 32) {
        sg += gw[i];
        sb += lnq_b[i] * w[i];
        cb += qb[i] * k[i];
    }
    #pragma unroll
    for (int o = 16; o > 0; o >>= 1) {
        sg += __shfl_xor_sync(0xffffffffu, sg, o);
        sb += __shfl_xor_sync(0xffffffffu, sb, o);
        cb += __shfl_xor_sync(0xffffffffu, cb, o);
    }
    if (lane == 0) { g_Sg[b] = sg; g_Sb[b] = sb + cb; }
}

// ================= attn + re->fp16 convert (fused, R7-proven) =================
__global__ void attn_cvt_kernel(const float* __restrict__ re) {
    int warp = threadIdx.x >> 5, lane = threadIdx.x & 31;
    int m = blockIdx.x * 8 + warp;
    int b = m >> 6;
    const float4* x  = (const float4*)(re + (size_t)m * E_);
    const float4* wv = (const float4*)(g_gw + (size_t)b * E_);
    uint2* ah = (uint2*)(g_Ah + (size_t)m * E_);
    float s1 = 0.f, s2 = 0.f, sd = 0.f;
    #pragma unroll
    for (int j = 0; j < 8; j++) {
        int idx = lane + j * 32;
        float4 t = x[idx];
        float4 w4 = wv[idx];
        s1 += t.x + t.y + t.z + t.w;
        s2 += t.x * t.x + t.y * t.y + t.z * t.z + t.w * t.w;
        sd += t.x * w4.x + t.y * w4.y + t.z * w4.z + t.w * w4.w;
        __half2 h0 = __floats2half2_rn(t.x, t.y);
        __half2 h1 = __floats2half2_rn(t.z, t.w);
        uint2 p;
        p.x = *(uint32_t*)&h0; p.y = *(uint32_t*)&h1;
        ah[idx] = p;
    }
    #pragma unroll
    for (int o = 16; o > 0; o >>= 1) {
        s1 += __shfl_xor_sync(0xffffffffu, s1, o);
        s2 += __shfl_xor_sync(0xffffffffu, s2, o);
        sd += __shfl_xor_sync(0xffffffffu, sd, o);
    }
    if (lane == 0) {
        float mu = s1 * (1.0f / E_);
        float var = s2 * (1.0f / E_) - mu * mu;
        float rstd = rsqrtf(var + 1e-5f);
        float score = 0.03125f * (rstd * (sd - mu * g_Sg[b]) + g_Sb[b]);
        g_attn[m] = tanhf(score);
    }
}

// ================= main GEMM (R7-proven: g_Ah fp16, 4-stage cp.async) ========
// out = re @ oW^T + attn*vo + ob;  CTA tile 128x256, 256 threads, warp 64x64,
// BK=32, 4-stage cp.async, 80B-padded smem rows.
#define MG_STAGES 4
#define MG_AROWB  80
#define MG_ASZ    (128*MG_AROWB)            // 10240
#define MG_BSZ    (256*MG_AROWB)            // 20480
#define MG_STGSZ  (MG_ASZ + MG_BSZ)         // 30720
#define MG_ITERS  32

__device__ __forceinline__ void mg_issue(uint32_t sbase, int stage, int it,
                                         int bm, int bn, int tid) {
    int kk = it << 5;
    uint32_t ab = sbase + stage * MG_STGSZ;
    uint32_t bb = ab + MG_ASZ;
    #pragma unroll
    for (int j = 0; j < 2; j++) {
        int id = tid + j * 256;
        int r = id >> 2, c = id & 3;
        cp16(ab + r * MG_AROWB + c * 16,
             g_Ah + (size_t)(bm + r) * E_ + kk + c * 8);
    }
    #pragma unroll
    for (int j = 0; j < 4; j++) {
        int id = tid + j * 256;
        int r = id >> 2, c = id & 3;
        cp16(bb + r * MG_AROWB + c * 16,
             g_Bh + (size_t)(bn + r) * E_ + kk + c * 8);
    }
}

__global__ void __launch_bounds__(256, 1) main_gemm_mma(const float* __restrict__ ob,
                                                        float* __restrict__ out) {
    extern __shared__ char smem[];
    uint32_t sbase = smem_u32(smem);
    int tid = threadIdx.x, wid = tid >> 5, lane = tid & 31;
    int bm = blockIdx.y * 128, bn = blockIdx.x * 256;
    int wm = wid & 1, wn = wid >> 1;          // warp tile: rows wm*64, cols wn*64

    float acc[4][8][4] = {};

    mg_issue(sbase, 0, 0, bm, bn, tid); CP_COMMIT();
    mg_issue(sbase, 1, 1, bm, bn, tid); CP_COMMIT();
    mg_issue(sbase, 2, 2, bm, bn, tid); CP_COMMIT();

    int l15 = lane & 15, l16 = lane >> 4;

    for (int i = 0; i < MG_ITERS; i++) {
        CP_WAIT2();
        __syncthreads();
        int s = i & 3;
        uint32_t ab = sbase + s * MG_STGSZ;
        uint32_t bb = ab + MG_ASZ;
        #pragma unroll
        for (int ks = 0; ks < 2; ks++) {
            int kc = ks * 2;
            uint32_t aaddr = ab + (wm * 64 + l15) * MG_AROWB + (kc + l16) * 16;
            uint32_t baddr = bb + (wn * 64 + l15) * MG_AROWB + (kc + l16) * 16;
            uint32_t ar[4][4], br[4][4];
            #pragma unroll
            for (int mi = 0; mi < 4; mi++)
                ldm4(ar[mi][0], ar[mi][1], ar[mi][2], ar[mi][3],
                     aaddr + mi * 16 * MG_AROWB);
            #pragma unroll
            for (int nb = 0; nb < 4; nb++)
                ldm4(br[nb][0], br[nb][1], br[nb][2], br[nb][3],
                     baddr + nb * 16 * MG_AROWB);
            #pragma unroll
            for (int mi = 0; mi < 4; mi++) {
                #pragma unroll
                for (int nb = 0; nb < 4; nb++) {
                    mma16816(acc[mi][2 * nb + 0], ar[mi], br[nb][0], br[nb][2]);
                    mma16816(acc[mi][2 * nb + 1], ar[mi], br[nb][1], br[nb][3]);
                }
            }
        }
        if (i + 3 < MG_ITERS)
            mg_issue(sbase, (i + 3) & 3, i + 3, bm, bn, tid);
        CP_COMMIT();
    }

    int lr = lane >> 2, lc = (lane & 3) * 2;
    #pragma unroll
    for (int mi = 0; mi < 4; mi++) {
        int row0 = bm + wm * 64 + mi * 16 + lr;
        int row1 = row0 + 8;
        float am0 = g_attn[row0], am1 = g_attn[row1];
        const float* vo0 = g_vo + (size_t)(row0 >> 6) * E_;
        const float* vo1 = g_vo + (size_t)(row1 >> 6) * E_;
        float* o0 = out + (size_t)row0 * E_;
        float* o1 = out + (size_t)row1 * E_;
        #pragma unroll
        for (int ni = 0; ni < 8; ni++) {
            int col = bn + wn * 64 + ni * 8 + lc;
            float2 r0, r1;
            r0.x = acc[mi][ni][0] + am0 * vo0[col]     + ob[col];
            r0.y = acc[mi][ni][1] + am0 * vo0[col + 1] + ob[col + 1];
            r1.x = acc[mi][ni][2] + am1 * vo1[col]     + ob[col];
            r1.y = acc[mi][ni][3] + am1 * vo1[col + 1] + ob[col + 1];
            *(float2*)(o0 + col) = r0;
            *(float2*)(o1 + col) = r1;
        }
    }
}

extern "C" void kernel_launch(void* const* d_in, const int* in_sizes, int n_in,
                              void* d_out, int out_size) {
    const float* re    = (const float*)d_in[0];
    const float* ctx   = (const float*)d_in[1];
    const float* qW    = (const float*)d_in[2];
    const float* qb    = (const float*)d_in[3];
    const float* kW    = (const float*)d_in[4];
    const float* kb    = (const float*)d_in[5];
    const float* vW    = (const float*)d_in[6];
    const float* vb    = (const float*)d_in[7];
    const float* oW    = (const float*)d_in[8];
    const float* ob    = (const float*)d_in[9];
    const float* lnq_g = (const float*)d_in[10];
    const float* lnq_b = (const float*)d_in[11];
    const float* lnk_g = (const float*)d_in[12];
    const float* lnk_b = (const float*)d_in[13];
    float* out = (float*)d_out;

    void *p_nkh, *p_kwh, *p_vwh, *p_qwth, *p_k, *p_kh, *p_vh, *p_w, *p_gw, *p_vo, *p_bh;
    cudaGetSymbolAddress(&p_nkh,  g_nk_h);
    cudaGetSymbolAddress(&p_kwh,  g_kWh);
    cudaGetSymbolAddress(&p_vwh,  g_vWh);
    cudaGetSymbolAddress(&p_qwth, g_qWTh);
    cudaGetSymbolAddress(&p_k,    g_k);
    cudaGetSymbolAddress(&p_kh,   g_k_h);
    cudaGetSymbolAddress(&p_vh,   g_v_h);
    cudaGetSymbolAddress(&p_w,    g_w);
    cudaGetSymbolAddress(&p_gw,   g_gw);
    cudaGetSymbolAddress(&p_vo,   g_vo);
    cudaGetSymbolAddress(&p_bh,   g_Bh);

    const int ag_smem = AG_STAGES * AG_STG;     // 61440
    const int mg_smem = MG_STAGES * MG_STGSZ;   // 122880
    cudaFuncSetAttribute(gemm_h_dual, cudaFuncAttributeMaxDynamicSharedMemorySize, ag_smem);
    cudaFuncSetAttribute(main_gemm_mma, cudaFuncAttributeMaxDynamicSharedMemorySize, mg_smem);

    // 0. weight converts (one kernel) + qW transpose
    cvt3_kernel<<<2048, 256>>>(oW, kW, vW, (__half*)p_bh, (__half*)p_kwh, (__half*)p_vwh);
    transpose_cvt_kernel<<<dim3(32, 32), dim3(32, 8)>>>(qW, (__half*)p_qwth);
    // 1. nk = LN(context) -> fp16
    ln_ctx_kernel<<<B_, 256>>>(ctx, lnk_g, lnk_b);
    // 2. k = nk@kW^T+kb  ||  v = nk@vW^T+vb
    {
        GemmArgs gk = { (__half*)p_nkh, (__half*)p_kwh, kb, (float*)p_k, (__half*)p_kh, nullptr, nullptr };
        GemmArgs gv = { (__half*)p_nkh, (__half*)p_vwh, vb, nullptr, (__half*)p_vh, nullptr, nullptr };
        gemm_h_dual<<<dim3(8, 8, 2), 256, ag_smem>>>(gk, gv, D_);
    }
    // 3. w = k@qW (+gw)  ||  vo = v@oW^T
    {
        GemmArgs gw_ = { (__half*)p_kh, (__half*)p_qwth, nullptr, (float*)p_w, nullptr, lnq_g, (float*)p_gw };
        GemmArgs gvo = { (__half*)p_vh, (__half*)p_bh, nullptr, (float*)p_vo, nullptr, nullptr, nullptr };
        gemm_h_dual<<<dim3(8, 8, 2), 256, ag_smem>>>(gw_, gvo, E_);
    }
    // 4. per-batch scalars
    scalars_kernel<<<B_ / 8, 256>>>(qb, lnq_b);
    // 5. attn per (b,n) row + re -> fp16 (fused)
    attn_cvt_kernel<<<M_ / 8, 256>>>(re);
    // 6. out = re @ oW^T + attn*vo + ob
    main_gemm_mma<<<dim3(4, 512), 256, mg_smem>>>(ob, out);
}

// round 14
// speedup vs baseline: 1.4227x; 1.0853x over previous
#include <cuda_runtime.h>
#include <cuda_fp16.h>
#include <math.h>
#include <stdint.h>

#define B_ 1024
#define N_ 64
#define E_ 1024
#define D_ 512
#define M_ (B_*N_)   // 65536 rows

// -------- scratch (device globals; no allocation allowed) --------
__device__ __half g_nk_h [B_*D_];
__device__ __half g_kWh  [E_*D_];
__device__ __half g_vWh  [E_*D_];
__device__ __half g_qWTh [E_*E_];
__device__ float  g_k    [B_*E_];
__device__ __half g_k_h  [B_*E_];
__device__ __half g_v_h  [B_*E_];
__device__ float  g_w    [B_*E_];
__device__ float  g_gw   [B_*E_];
__device__ float  g_vo   [B_*E_];
__device__ float  g_Sg   [B_];
__device__ float  g_Sb   [B_];
__device__ float  g_attn [M_];
__device__ __half g_Ah   [(size_t)M_*E_];
__device__ __half g_Bh   [(size_t)E_*E_];

// ================= PTX helpers (compute_103-safe) ==========
__device__ __forceinline__ uint32_t smem_u32(const void* p) {
    uint32_t a;
    asm("{ .reg .u64 t; cvta.to.shared.u64 t, %1; cvt.u32.u64 %0, t; }" : "=r"(a) : "l"(p));
    return a;
}
__device__ __forceinline__ void cp16(uint32_t dst, const void* src) {
    asm volatile("cp.async.cg.shared.global [%0], [%1], 16;" :: "r"(dst), "l"(src));
}
#define CP_COMMIT() asm volatile("cp.async.commit_group;" ::: "memory")
#define CP_WAIT2()  asm volatile("cp.async.wait_group 2;" ::: "memory")
#define CP_WAIT1()  asm volatile("cp.async.wait_group 1;" ::: "memory")

__device__ __forceinline__ void ldm4(uint32_t& r0, uint32_t& r1, uint32_t& r2,
                                     uint32_t& r3, uint32_t a) {
    asm volatile("ldmatrix.sync.aligned.m8n8.x4.shared.b16 {%0,%1,%2,%3}, [%4];"
                 : "=r"(r0), "=r"(r1), "=r"(r2), "=r"(r3) : "r"(a));
}
__device__ __forceinline__ void mma16816(float* c, const uint32_t* a,
                                         uint32_t b0, uint32_t b1) {
    asm volatile("mma.sync.aligned.m16n8k16.row.col.f32.f16.f16.f32 "
                 "{%0,%1,%2,%3},{%4,%5,%6,%7},{%8,%9},{%0,%1,%2,%3};"
                 : "+f"(c[0]), "+f"(c[1]), "+f"(c[2]), "+f"(c[3])
                 : "r"(a[0]), "r"(a[1]), "r"(a[2]), "r"(a[3]), "r"(b0), "r"(b1));
}

// ================= prep kernel: weight converts + qW transpose + LN =========
// blocks [0,1024): oW->Bh; [1024,1536): kW->kWh; [1536,2048): vW->vWh;
// [2048,3072): transpose-cvt qW -> qWTh; [3072,4096): LN(ctx) -> nk_h
__global__ void prep_kernel(const float* __restrict__ oW,
                            const float* __restrict__ kW,
                            const float* __restrict__ vW,
                            const float* __restrict__ qW,
                            const float* __restrict__ ctx,
                            const float* __restrict__ lnk_g,
                            const float* __restrict__ lnk_b,
                            __half* __restrict__ bh,
                            __half* __restrict__ kwh,
                            __half* __restrict__ vwh,
                            __half* __restrict__ qwth) {
    int blk = blockIdx.x;
    int tid = threadIdx.x;
    if (blk < 2048) {
        const float* src;
        __half* dst;
        size_t base;
        if (blk < 1024) { src = oW; dst = bh; base = (size_t)blk * 1024; }
        else if (blk < 1536) { src = kW; dst = kwh; base = (size_t)(blk - 1024) * 1024; }
        else { src = vW; dst = vwh; base = (size_t)(blk - 1536) * 1024; }
        size_t i = base + tid * 4;
        float4 v = *(const float4*)(src + i);
        __half2 a = __floats2half2_rn(v.x, v.y);
        __half2 b = __floats2half2_rn(v.z, v.w);
        uint2 p;
        p.x = *(uint32_t*)&a; p.y = *(uint32_t*)&b;
        *(uint2*)(dst + i) = p;
    } else if (blk < 3072) {
        __shared__ float t[32][33];
        int tb = blk - 2048;
        int tx = tid & 31, ty = tid >> 5;   // 32 x 8
        int bx = (tb & 31) * 32, by = (tb >> 5) * 32;
        #pragma unroll
        for (int i = 0; i < 32; i += 8)
            t[ty + i][tx] = qW[(size_t)(by + ty + i) * E_ + bx + tx];
        __syncthreads();
        #pragma unroll
        for (int i = 0; i < 32; i += 8)
            qwth[(size_t)(bx + ty + i) * E_ + by + tx] = __float2half(t[tx][ty + i]);
    } else {
        int b = blk - 3072;
        const float* x = ctx + (size_t)b * D_;
        float v0 = x[tid], v1 = x[tid + 256];
        __shared__ float r1[256], r2[256];
        r1[tid] = v0 + v1;
        r2[tid] = v0 * v0 + v1 * v1;
        __syncthreads();
        for (int o = 128; o > 0; o >>= 1) {
            if (tid < o) { r1[tid] += r1[tid + o]; r2[tid] += r2[tid + o]; }
            __syncthreads();
        }
        float mu = r1[0] * (1.0f / D_);
        float var = r2[0] * (1.0f / D_) - mu * mu;
        float rstd = rsqrtf(var + 1e-5f);
        g_nk_h[(size_t)b * D_ + tid]       = __float2half((v0 - mu) * rstd * lnk_g[tid]       + lnk_b[tid]);
        g_nk_h[(size_t)b * D_ + tid + 256] = __float2half((v1 - mu) * rstd * lnk_g[tid + 256] + lnk_b[tid + 256]);
    }
}

// ================= aux fp16 GEMM (dual via blockIdx.z) =================
struct GemmArgs {
    const __half* A;
    const __half* Bm;
    const float*  bias;
    float*        Cf;
    __half*       Ch;
    const float*  colmul;
    float*        C2f;
};

#define AG_AROWB 80
#define AG_ASZ   (128*AG_AROWB)
#define AG_STG   (2*AG_ASZ)
#define AG_STAGES 3

__device__ __forceinline__ void ag_issue(uint32_t sbase, int stage, int it,
                                         int bm, int bn, int tid,
                                         const __half* A, const __half* Bm, int K) {
    int kk = it << 5;
    uint32_t ab = sbase + stage * AG_STG;
    uint32_t bb = ab + AG_ASZ;
    #pragma unroll
    for (int j = 0; j < 2; j++) {
        int id = tid + j * 256;
        int r = id >> 2, c = id & 3;
        cp16(ab + r * AG_AROWB + c * 16, A  + (size_t)(bm + r) * K + kk + c * 8);
        cp16(bb + r * AG_AROWB + c * 16, Bm + (size_t)(bn + r) * K + kk + c * 8);
    }
}

__global__ void __launch_bounds__(256, 1) gemm_h_dual(GemmArgs g0, GemmArgs g1, int K) {
    extern __shared__ char smem[];
    uint32_t sbase = smem_u32(smem);
    const GemmArgs g = (blockIdx.z == 0) ? g0 : g1;
    const __half* A = g.A;
    const __half* Bm = g.Bm;
    int tid = threadIdx.x, wid = tid >> 5, lane = tid & 31;
    int bm = blockIdx.y * 128, bn = blockIdx.x * 128;
    int wm = wid & 1, wn = wid >> 1;
    int iters = K >> 5;

    float acc[4][4][4] = {};

    ag_issue(sbase, 0, 0, bm, bn, tid, A, Bm, K); CP_COMMIT();
    ag_issue(sbase, 1, 1, bm, bn, tid, A, Bm, K); CP_COMMIT();

    int l15 = lane & 15, l16 = lane >> 4;

    for (int i = 0; i < iters; i++) {
        CP_WAIT1();
        __syncthreads();
        int s = i % 3;
        uint32_t ab = sbase + s * AG_STG;
        uint32_t bb = ab + AG_ASZ;
        #pragma unroll
        for (int ks = 0; ks < 2; ks++) {
            int kc = ks * 2;
            uint32_t aaddr = ab + (wm * 64 + l15) * AG_AROWB + (kc + l16) * 16;
            uint32_t baddr = bb + (wn * 32 + l15) * AG_AROWB + (kc + l16) * 16;
            uint32_t ar[4][4], br[2][4];
            #pragma unroll
            for (int mi = 0; mi < 4; mi++)
                ldm4(ar[mi][0], ar[mi][1], ar[mi][2], ar[mi][3],
                     aaddr + mi * 16 * AG_AROWB);
            #pragma unroll
            for (int nb = 0; nb < 2; nb++)
                ldm4(br[nb][0], br[nb][1], br[nb][2], br[nb][3],
                     baddr + nb * 16 * AG_AROWB);
            #pragma unroll
            for (int mi = 0; mi < 4; mi++) {
                #pragma unroll
                for (int nb = 0; nb < 2; nb++) {
                    mma16816(acc[mi][2 * nb + 0], ar[mi], br[nb][0], br[nb][2]);
                    mma16816(acc[mi][2 * nb + 1], ar[mi], br[nb][1], br[nb][3]);
                }
            }
        }
        if (i + 2 < iters)
            ag_issue(sbase, (i + 2) % 3, i + 2, bm, bn, tid, A, Bm, K);
        CP_COMMIT();
    }

    int lr = lane >> 2, lc = (lane & 3) * 2;
    #pragma unroll
    for (int mi = 0; mi < 4; mi++) {
        int row0 = bm + wm * 64 + mi * 16 + lr;
        int row1 = row0 + 8;
        #pragma unroll
        for (int ni = 0; ni < 4; ni++) {
            int col = bn + wn * 32 + ni * 8 + lc;
            float b0 = g.bias ? g.bias[col] : 0.0f;
            float b1 = g.bias ? g.bias[col + 1] : 0.0f;
            float v00 = acc[mi][ni][0] + b0, v01 = acc[mi][ni][1] + b1;
            float v10 = acc[mi][ni][2] + b0, v11 = acc[mi][ni][3] + b1;
            if (g.Cf) {
                *(float2*)(g.Cf + (size_t)row0 * 1024 + col) = make_float2(v00, v01);
                *(float2*)(g.Cf + (size_t)row1 * 1024 + col) = make_float2(v10, v11);
            }
            if (g.Ch) {
                __half2 h0 = __floats2half2_rn(v00, v01);
                __half2 h1 = __floats2half2_rn(v10, v11);
                *(__half2*)(g.Ch + (size_t)row0 * 1024 + col) = h0;
                *(__half2*)(g.Ch + (size_t)row1 * 1024 + col) = h1;
            }
            if (g.C2f) {
                float c0 = g.colmul[col], c1 = g.colmul[col + 1];
                *(float2*)(g.C2f + (size_t)row0 * 1024 + col) = make_float2(c0 * v00, c1 * v01);
                *(float2*)(g.C2f + (size_t)row1 * 1024 + col) = make_float2(c0 * v10, c1 * v11);
            }
        }
    }
}

// ================= scalars =================
__global__ void scalars_kernel(const float* __restrict__ qb,
                               const float* __restrict__ lnq_b) {
    int warp = threadIdx.x >> 5, lane = threadIdx.x & 31;
    int b = blockIdx.x * 8 + warp;
    const float* gw = g_gw + (size_t)b * E_;
    const float* w  = g_w  + (size_t)b * E_;
    const float* k  = g_k  + (size_t)b * E_;
    float sg = 0.f, sb = 0.f, cb = 0.f;
    for (int i = lane; i < E_; i += 32) {
        sg += gw[i];
        sb += lnq_b[i] * w[i];
        cb += qb[i] * k[i];
    }
    #pragma unroll
    for (int o = 16; o > 0; o >>= 1) {
        sg += __shfl_xor_sync(0xffffffffu, sg, o);
        sb += __shfl_xor_sync(0xffffffffu, sb, o);
        cb += __shfl_xor_sync(0xffffffffu, cb, o);
    }
    if (lane == 0) { g_Sg[b] = sg; g_Sb[b] = sb + cb; }
}

// ================= attn + re->fp16 convert (fused) =================
__global__ void attn_cvt_kernel(const float* __restrict__ re) {
    int warp = threadIdx.x >> 5, lane = threadIdx.x & 31;
    int m = blockIdx.x * 8 + warp;
    int b = m >> 6;
    const float4* x  = (const float4*)(re + (size_t)m * E_);
    const float4* wv = (const float4*)(g_gw + (size_t)b * E_);
    uint2* ah = (uint2*)(g_Ah + (size_t)m * E_);
    float s1 = 0.f, s2 = 0.f, sd = 0.f;
    #pragma unroll
    for (int j = 0; j < 8; j++) {
        int idx = lane + j * 32;
        float4 t = x[idx];
        float4 w4 = wv[idx];
        s1 += t.x + t.y + t.z + t.w;
        s2 += t.x * t.x + t.y * t.y + t.z * t.z + t.w * t.w;
        sd += t.x * w4.x + t.y * w4.y + t.z * w4.z + t.w * w4.w;
        __half2 h0 = __floats2half2_rn(t.x, t.y);
        __half2 h1 = __floats2half2_rn(t.z, t.w);
        uint2 p;
        p.x = *(uint32_t*)&h0; p.y = *(uint32_t*)&h1;
        ah[idx] = p;
    }
    #pragma unroll
    for (int o = 16; o > 0; o >>= 1) {
        s1 += __shfl_xor_sync(0xffffffffu, s1, o);
        s2 += __shfl_xor_sync(0xffffffffu, s2, o);
        sd += __shfl_xor_sync(0xffffffffu, sd, o);
    }
    if (lane == 0) {
        float mu = s1 * (1.0f / E_);
        float var = s2 * (1.0f / E_) - mu * mu;
        float rstd = rsqrtf(var + 1e-5f);
        float score = 0.03125f * (rstd * (sd - mu * g_Sg[b]) + g_Sb[b]);
        g_attn[m] = tanhf(score);
    }
}

// ================= main GEMM: 128x128 CTA tile, 2 CTAs/SM =================
// out = re @ oW^T + attn*vo + ob;  256 threads, warp tile 64x32, BK=32,
// 3-stage cp.async (61440B smem -> 2 CTAs/SM for latency hiding).
#define M3_AROWB 80
#define M3_SZ    (128*M3_AROWB)      // 10240
#define M3_STG   (2*M3_SZ)           // 20480
#define M3_SMEM  (3*M3_STG)          // 61440
#define M3_ITERS 32

__device__ __forceinline__ void m3_issue(uint32_t sbase, int stage, int it,
                                         int bm, int bn, int tid) {
    int kk = it << 5;
    uint32_t ab = sbase + stage * M3_STG;
    uint32_t bb = ab + M3_SZ;
    #pragma unroll
    for (int j = 0; j < 2; j++) {
        int id = tid + j * 256;
        int r = id >> 2, c = id & 3;
        cp16(ab + r * M3_AROWB + c * 16,
             g_Ah + (size_t)(bm + r) * E_ + kk + c * 8);
        cp16(bb + r * M3_AROWB + c * 16,
             g_Bh + (size_t)(bn + r) * E_ + kk + c * 8);
    }
}

__global__ void __launch_bounds__(256, 2) main_gemm_v3(const float* __restrict__ ob,
                                                       float* __restrict__ out) {
    extern __shared__ char smem[];
    uint32_t sbase = smem_u32(smem);
    int tid = threadIdx.x, wid = tid >> 5, lane = tid & 31;
    int bm = blockIdx.y * 128, bn = blockIdx.x * 128;
    int wm = wid & 1, wn = wid >> 1;   // warp tile: rows wm*64, cols wn*32

    float acc[4][4][4] = {};

    m3_issue(sbase, 0, 0, bm, bn, tid); CP_COMMIT();
    m3_issue(sbase, 1, 1, bm, bn, tid); CP_COMMIT();

    int l15 = lane & 15, l16 = lane >> 4;

    for (int i = 0; i < M3_ITERS; i++) {
        CP_WAIT1();
        __syncthreads();
        int s = i % 3;
        uint32_t ab = sbase + s * M3_STG;
        uint32_t bb = ab + M3_SZ;
        #pragma unroll
        for (int ks = 0; ks < 2; ks++) {
            int kc = ks * 2;
            uint32_t aaddr = ab + (wm * 64 + l15) * M3_AROWB + (kc + l16) * 16;
            uint32_t baddr = bb + (wn * 32 + l15) * M3_AROWB + (kc + l16) * 16;
            uint32_t ar[4][4], br[2][4];
            #pragma unroll
            for (int mi = 0; mi < 4; mi++)
                ldm4(ar[mi][0], ar[mi][1], ar[mi][2], ar[mi][3],
                     aaddr + mi * 16 * M3_AROWB);
            #pragma unroll
            for (int nb = 0; nb < 2; nb++)
                ldm4(br[nb][0], br[nb][1], br[nb][2], br[nb][3],
                     baddr + nb * 16 * M3_AROWB);
            #pragma unroll
            for (int mi = 0; mi < 4; mi++) {
                #pragma unroll
                for (int nb = 0; nb < 2; nb++) {
                    mma16816(acc[mi][2 * nb + 0], ar[mi], br[nb][0], br[nb][2]);
                    mma16816(acc[mi][2 * nb + 1], ar[mi], br[nb][1], br[nb][3]);
                }
            }
        }
        if (i + 2 < M3_ITERS)
            m3_issue(sbase, (i + 2) % 3, i + 2, bm, bn, tid);
        CP_COMMIT();
    }

    int lr = lane >> 2, lc = (lane & 3) * 2;
    #pragma unroll
    for (int mi = 0; mi < 4; mi++) {
        int row0 = bm + wm * 64 + mi * 16 + lr;
        int row1 = row0 + 8;
        float am0 = g_attn[row0], am1 = g_attn[row1];
        const float* vo0 = g_vo + (size_t)(row0 >> 6) * E_;
        const float* vo1 = g_vo + (size_t)(row1 >> 6) * E_;
        float* o0 = out + (size_t)row0 * E_;
        float* o1 = out + (size_t)row1 * E_;
        #pragma unroll
        for (int ni = 0; ni < 4; ni++) {
            int col = bn + wn * 32 + ni * 8 + lc;
            float2 r0, r1;
            r0.x = acc[mi][ni][0] + am0 * vo0[col]     + ob[col];
            r0.y = acc[mi][ni][1] + am0 * vo0[col + 1] + ob[col + 1];
            r1.x = acc[mi][ni][2] + am1 * vo1[col]     + ob[col];
            r1.y = acc[mi][ni][3] + am1 * vo1[col + 1] + ob[col + 1];
            *(float2*)(o0 + col) = r0;
            *(float2*)(o1 + col) = r1;
        }
    }
}

extern "C" void kernel_launch(void* const* d_in, const int* in_sizes, int n_in,
                              void* d_out, int out_size) {
    const float* re    = (const float*)d_in[0];
    const float* ctx   = (const float*)d_in[1];
    const float* qW    = (const float*)d_in[2];
    const float* qb    = (const float*)d_in[3];
    const float* kW    = (const float*)d_in[4];
    const float* kb    = (const float*)d_in[5];
    const float* vW    = (const float*)d_in[6];
    const float* vb    = (const float*)d_in[7];
    const float* oW    = (const float*)d_in[8];
    const float* ob    = (const float*)d_in[9];
    const float* lnq_g = (const float*)d_in[10];
    const float* lnq_b = (const float*)d_in[11];
    const float* lnk_g = (const float*)d_in[12];
    const float* lnk_b = (const float*)d_in[13];
    float* out = (float*)d_out;

    void *p_nkh, *p_kwh, *p_vwh, *p_qwth, *p_k, *p_kh, *p_vh, *p_w, *p_gw, *p_vo, *p_bh;
    cudaGetSymbolAddress(&p_nkh,  g_nk_h);
    cudaGetSymbolAddress(&p_kwh,  g_kWh);
    cudaGetSymbolAddress(&p_vwh,  g_vWh);
    cudaGetSymbolAddress(&p_qwth, g_qWTh);
    cudaGetSymbolAddress(&p_k,    g_k);
    cudaGetSymbolAddress(&p_kh,   g_k_h);
    cudaGetSymbolAddress(&p_vh,   g_v_h);
    cudaGetSymbolAddress(&p_w,    g_w);
    cudaGetSymbolAddress(&p_gw,   g_gw);
    cudaGetSymbolAddress(&p_vo,   g_vo);
    cudaGetSymbolAddress(&p_bh,   g_Bh);

    const int ag_smem = AG_STAGES * AG_STG;   // 61440
    cudaFuncSetAttribute(gemm_h_dual, cudaFuncAttributeMaxDynamicSharedMemorySize, ag_smem);
    cudaFuncSetAttribute(main_gemm_v3, cudaFuncAttributeMaxDynamicSharedMemorySize, M3_SMEM);

    // 0. prep: weight converts + qW transpose + LN(ctx)
    prep_kernel<<<4096, 256>>>(oW, kW, vW, qW, ctx, lnk_g, lnk_b,
                               (__half*)p_bh, (__half*)p_kwh, (__half*)p_vwh,
                               (__half*)p_qwth);
    // 1. k = nk@kW^T+kb  ||  v = nk@vW^T+vb
    {
        GemmArgs gk = { (__half*)p_nkh, (__half*)p_kwh, kb, (float*)p_k, (__half*)p_kh, nullptr, nullptr };
        GemmArgs gv = { (__half*)p_nkh, (__half*)p_vwh, vb, nullptr, (__half*)p_vh, nullptr, nullptr };
        gemm_h_dual<<<dim3(8, 8, 2), 256, ag_smem>>>(gk, gv, D_);
    }
    // 2. w = k@qW (+gw)  ||  vo = v@oW^T
    {
        GemmArgs gw_ = { (__half*)p_kh, (__half*)p_qwth, nullptr, (float*)p_w, nullptr, lnq_g, (float*)p_gw };
        GemmArgs gvo = { (__half*)p_vh, (__half*)p_bh, nullptr, (float*)p_vo, nullptr, nullptr, nullptr };
        gemm_h_dual<<<dim3(8, 8, 2), 256, ag_smem>>>(gw_, gvo, E_);
    }
    // 3. per-batch scalars
    scalars_kernel<<<B_ / 8, 256>>>(qb, lnq_b);
    // 4. attn per (b,n) row + re -> fp16 (fused)
    attn_cvt_kernel<<<M_ / 8, 256>>>(re);
    // 5. out = re @ oW^T + attn*vo + ob  (128x128, 2 CTAs/SM)
    main_gemm_v3<<<dim3(8, 512), 256, M3_SMEM>>>(ob, out);
}

// round 15
// speedup vs baseline: 1.5490x; 1.0888x over previous
#include <cuda_runtime.h>
#include <cuda_fp16.h>
#include <math.h>
#include <stdint.h>

#define B_ 1024
#define N_ 64
#define E_ 1024
#define D_ 512
#define M_ (B_*N_)   // 65536 rows

// -------- scratch (device globals; no allocation allowed) --------
__device__ __half g_nk_h [B_*D_];
__device__ __half g_kWh  [E_*D_];
__device__ __half g_vWh  [E_*D_];
__device__ __half g_qWTh [E_*E_];
__device__ float  g_k    [B_*E_];
__device__ __half g_k_h  [B_*E_];
__device__ __half g_v_h  [B_*E_];
__device__ float  g_w    [B_*E_];
__device__ float  g_gw   [B_*E_];
__device__ float  g_vo   [B_*E_];
__device__ float  g_Sg   [B_];
__device__ float  g_Sb   [B_];
__device__ float  g_attn [M_];
__device__ __half g_Ah   [(size_t)M_*E_];
__device__ __half g_Bh   [(size_t)E_*E_];

// ================= PTX helpers (compute_103-safe) ==========
__device__ __forceinline__ uint32_t smem_u32(const void* p) {
    uint32_t a;
    asm("{ .reg .u64 t; cvta.to.shared.u64 t, %1; cvt.u32.u64 %0, t; }" : "=r"(a) : "l"(p));
    return a;
}
__device__ __forceinline__ void cp16(uint32_t dst, const void* src) {
    asm volatile("cp.async.cg.shared.global [%0], [%1], 16;" :: "r"(dst), "l"(src));
}
#define CP_COMMIT() asm volatile("cp.async.commit_group;" ::: "memory")
#define CP_WAIT2()  asm volatile("cp.async.wait_group 2;" ::: "memory")
#define CP_WAIT1()  asm volatile("cp.async.wait_group 1;" ::: "memory")

__device__ __forceinline__ void ldm4(uint32_t& r0, uint32_t& r1, uint32_t& r2,
                                     uint32_t& r3, uint32_t a) {
    asm volatile("ldmatrix.sync.aligned.m8n8.x4.shared.b16 {%0,%1,%2,%3}, [%4];"
                 : "=r"(r0), "=r"(r1), "=r"(r2), "=r"(r3) : "r"(a));
}
__device__ __forceinline__ void mma16816(float* c, const uint32_t* a,
                                         uint32_t b0, uint32_t b1) {
    asm volatile("mma.sync.aligned.m16n8k16.row.col.f32.f16.f16.f32 "
                 "{%0,%1,%2,%3},{%4,%5,%6,%7},{%8,%9},{%0,%1,%2,%3};"
                 : "+f"(c[0]), "+f"(c[1]), "+f"(c[2]), "+f"(c[3])
                 : "r"(a[0]), "r"(a[1]), "r"(a[2]), "r"(a[3]), "r"(b0), "r"(b1));
}

// ================= prep kernel: weight converts + qW transpose + LN =========
__global__ void prep_kernel(const float* __restrict__ oW,
                            const float* __restrict__ kW,
                            const float* __restrict__ vW,
                            const float* __restrict__ qW,
                            const float* __restrict__ ctx,
                            const float* __restrict__ lnk_g,
                            const float* __restrict__ lnk_b,
                            __half* __restrict__ bh,
                            __half* __restrict__ kwh,
                            __half* __restrict__ vwh,
                            __half* __restrict__ qwth) {
    int blk = blockIdx.x;
    int tid = threadIdx.x;
    if (blk < 2048) {
        const float* src;
        __half* dst;
        size_t base;
        if (blk < 1024) { src = oW; dst = bh; base = (size_t)blk * 1024; }
        else if (blk < 1536) { src = kW; dst = kwh; base = (size_t)(blk - 1024) * 1024; }
        else { src = vW; dst = vwh; base = (size_t)(blk - 1536) * 1024; }
        size_t i = base + tid * 4;
        float4 v = *(const float4*)(src + i);
        __half2 a = __floats2half2_rn(v.x, v.y);
        __half2 b = __floats2half2_rn(v.z, v.w);
        uint2 p;
        p.x = *(uint32_t*)&a; p.y = *(uint32_t*)&b;
        *(uint2*)(dst + i) = p;
    } else if (blk < 3072) {
        __shared__ float t[32][33];
        int tb = blk - 2048;
        int tx = tid & 31, ty = tid >> 5;   // 32 x 8
        int bx = (tb & 31) * 32, by = (tb >> 5) * 32;
        #pragma unroll
        for (int i = 0; i < 32; i += 8)
            t[ty + i][tx] = qW[(size_t)(by + ty + i) * E_ + bx + tx];
        __syncthreads();
        #pragma unroll
        for (int i = 0; i < 32; i += 8)
            qwth[(size_t)(bx + ty + i) * E_ + by + tx] = __float2half(t[tx][ty + i]);
    } else {
        int b = blk - 3072;
        const float* x = ctx + (size_t)b * D_;
        float v0 = x[tid], v1 = x[tid + 256];
        __shared__ float r1[256], r2[256];
        r1[tid] = v0 + v1;
        r2[tid] = v0 * v0 + v1 * v1;
        __syncthreads();
        for (int o = 128; o > 0; o >>= 1) {
            if (tid < o) { r1[tid] += r1[tid + o]; r2[tid] += r2[tid + o]; }
            __syncthreads();
        }
        float mu = r1[0] * (1.0f / D_);
        float var = r2[0] * (1.0f / D_) - mu * mu;
        float rstd = rsqrtf(var + 1e-5f);
        g_nk_h[(size_t)b * D_ + tid]       = __float2half((v0 - mu) * rstd * lnk_g[tid]       + lnk_b[tid]);
        g_nk_h[(size_t)b * D_ + tid + 256] = __float2half((v1 - mu) * rstd * lnk_g[tid + 256] + lnk_b[tid + 256]);
    }
}

// ================= aux fp16 GEMM (dual via blockIdx.z) =================
struct GemmArgs {
    const __half* A;
    const __half* Bm;
    const float*  bias;
    float*        Cf;
    __half*       Ch;
    const float*  colmul;
    float*        C2f;
};

#define AG_AROWB 80
#define AG_ASZ   (128*AG_AROWB)
#define AG_STG   (2*AG_ASZ)
#define AG_STAGES 3

__device__ __forceinline__ void ag_issue(uint32_t sbase, int stage, int it,
                                         int bm, int bn, int tid,
                                         const __half* A, const __half* Bm, int K) {
    int kk = it << 5;
    uint32_t ab = sbase + stage * AG_STG;
    uint32_t bb = ab + AG_ASZ;
    #pragma unroll
    for (int j = 0; j < 2; j++) {
        int id = tid + j * 256;
        int r = id >> 2, c = id & 3;
        cp16(ab + r * AG_AROWB + c * 16, A  + (size_t)(bm + r) * K + kk + c * 8);
        cp16(bb + r * AG_AROWB + c * 16, Bm + (size_t)(bn + r) * K + kk + c * 8);
    }
}

__global__ void __launch_bounds__(256, 1) gemm_h_dual(GemmArgs g0, GemmArgs g1, int K) {
    extern __shared__ char smem[];
    uint32_t sbase = smem_u32(smem);
    const GemmArgs g = (blockIdx.z == 0) ? g0 : g1;
    const __half* A = g.A;
    const __half* Bm = g.Bm;
    int tid = threadIdx.x, wid = tid >> 5, lane = tid & 31;
    int bm = blockIdx.y * 128, bn = blockIdx.x * 128;
    int wm = wid & 1, wn = wid >> 1;
    int iters = K >> 5;

    float acc[4][4][4] = {};

    ag_issue(sbase, 0, 0, bm, bn, tid, A, Bm, K); CP_COMMIT();
    ag_issue(sbase, 1, 1, bm, bn, tid, A, Bm, K); CP_COMMIT();

    int l15 = lane & 15, l16 = lane >> 4;

    for (int i = 0; i < iters; i++) {
        CP_WAIT1();
        __syncthreads();
        int s = i % 3;
        uint32_t ab = sbase + s * AG_STG;
        uint32_t bb = ab + AG_ASZ;
        #pragma unroll
        for (int ks = 0; ks < 2; ks++) {
            int kc = ks * 2;
            uint32_t aaddr = ab + (wm * 64 + l15) * AG_AROWB + (kc + l16) * 16;
            uint32_t baddr = bb + (wn * 32 + l15) * AG_AROWB + (kc + l16) * 16;
            uint32_t ar[4][4], br[2][4];
            #pragma unroll
            for (int mi = 0; mi < 4; mi++)
                ldm4(ar[mi][0], ar[mi][1], ar[mi][2], ar[mi][3],
                     aaddr + mi * 16 * AG_AROWB);
            #pragma unroll
            for (int nb = 0; nb < 2; nb++)
                ldm4(br[nb][0], br[nb][1], br[nb][2], br[nb][3],
                     baddr + nb * 16 * AG_AROWB);
            #pragma unroll
            for (int mi = 0; mi < 4; mi++) {
                #pragma unroll
                for (int nb = 0; nb < 2; nb++) {
                    mma16816(acc[mi][2 * nb + 0], ar[mi], br[nb][0], br[nb][2]);
                    mma16816(acc[mi][2 * nb + 1], ar[mi], br[nb][1], br[nb][3]);
                }
            }
        }
        if (i + 2 < iters)
            ag_issue(sbase, (i + 2) % 3, i + 2, bm, bn, tid, A, Bm, K);
        CP_COMMIT();
    }

    int lr = lane >> 2, lc = (lane & 3) * 2;
    #pragma unroll
    for (int mi = 0; mi < 4; mi++) {
        int row0 = bm + wm * 64 + mi * 16 + lr;
        int row1 = row0 + 8;
        #pragma unroll
        for (int ni = 0; ni < 4; ni++) {
            int col = bn + wn * 32 + ni * 8 + lc;
            float b0 = g.bias ? g.bias[col] : 0.0f;
            float b1 = g.bias ? g.bias[col + 1] : 0.0f;
            float v00 = acc[mi][ni][0] + b0, v01 = acc[mi][ni][1] + b1;
            float v10 = acc[mi][ni][2] + b0, v11 = acc[mi][ni][3] + b1;
            if (g.Cf) {
                *(float2*)(g.Cf + (size_t)row0 * 1024 + col) = make_float2(v00, v01);
                *(float2*)(g.Cf + (size_t)row1 * 1024 + col) = make_float2(v10, v11);
            }
            if (g.Ch) {
                __half2 h0 = __floats2half2_rn(v00, v01);
                __half2 h1 = __floats2half2_rn(v10, v11);
                *(__half2*)(g.Ch + (size_t)row0 * 1024 + col) = h0;
                *(__half2*)(g.Ch + (size_t)row1 * 1024 + col) = h1;
            }
            if (g.C2f) {
                float c0 = g.colmul[col], c1 = g.colmul[col + 1];
                *(float2*)(g.C2f + (size_t)row0 * 1024 + col) = make_float2(c0 * v00, c1 * v01);
                *(float2*)(g.C2f + (size_t)row1 * 1024 + col) = make_float2(c0 * v10, c1 * v11);
            }
        }
    }
}

// ================= scalars (block per batch, 256 threads) =================
__global__ void scalars_kernel(const float* __restrict__ qb,
                               const float* __restrict__ lnq_b) {
    int b = blockIdx.x, tid = threadIdx.x;
    const float4* gw = (const float4*)(g_gw + (size_t)b * E_);
    const float4* w  = (const float4*)(g_w  + (size_t)b * E_);
    const float4* k  = (const float4*)(g_k  + (size_t)b * E_);
    const float4* lb = (const float4*)lnq_b;
    const float4* qb4 = (const float4*)qb;
    float sg = 0.f, sb = 0.f;
    // 1024 floats = 256 float4: one per thread
    float4 gv = gw[tid], wv = w[tid], kv = k[tid], lv = lb[tid], qv = qb4[tid];
    sg = gv.x + gv.y + gv.z + gv.w;
    sb = lv.x * wv.x + lv.y * wv.y + lv.z * wv.z + lv.w * wv.w
       + qv.x * kv.x + qv.y * kv.y + qv.z * kv.z + qv.w * kv.w;
    __shared__ float r1[256], r2[256];
    r1[tid] = sg; r2[tid] = sb;
    __syncthreads();
    for (int o = 128; o > 0; o >>= 1) {
        if (tid < o) { r1[tid] += r1[tid + o]; r2[tid] += r2[tid + o]; }
        __syncthreads();
    }
    if (tid == 0) { g_Sg[b] = r1[0]; g_Sb[b] = r2[0]; }
}

// ================= attn + re->fp16 convert (fused) =================
__global__ void attn_cvt_kernel(const float* __restrict__ re) {
    int warp = threadIdx.x >> 5, lane = threadIdx.x & 31;
    int m = blockIdx.x * 8 + warp;
    int b = m >> 6;
    const float4* x  = (const float4*)(re + (size_t)m * E_);
    const float4* wv = (const float4*)(g_gw + (size_t)b * E_);
    uint2* ah = (uint2*)(g_Ah + (size_t)m * E_);
    float s1 = 0.f, s2 = 0.f, sd = 0.f;
    #pragma unroll
    for (int j = 0; j < 8; j++) {
        int idx = lane + j * 32;
        float4 t = x[idx];
        float4 w4 = wv[idx];
        s1 += t.x + t.y + t.z + t.w;
        s2 += t.x * t.x + t.y * t.y + t.z * t.z + t.w * t.w;
        sd += t.x * w4.x + t.y * w4.y + t.z * w4.z + t.w * w4.w;
        __half2 h0 = __floats2half2_rn(t.x, t.y);
        __half2 h1 = __floats2half2_rn(t.z, t.w);
        uint2 p;
        p.x = *(uint32_t*)&h0; p.y = *(uint32_t*)&h1;
        ah[idx] = p;
    }
    #pragma unroll
    for (int o = 16; o > 0; o >>= 1) {
        s1 += __shfl_xor_sync(0xffffffffu, s1, o);
        s2 += __shfl_xor_sync(0xffffffffu, s2, o);
        sd += __shfl_xor_sync(0xffffffffu, sd, o);
    }
    if (lane == 0) {
        float mu = s1 * (1.0f / E_);
        float var = s2 * (1.0f / E_) - mu * mu;
        float rstd = rsqrtf(var + 1e-5f);
        float score = 0.03125f * (rstd * (sd - mu * g_Sg[b]) + g_Sb[b]);
        g_attn[m] = tanhf(score);
    }
}

// ================= main GEMM: 128x128 CTA, 4-stage, 2 CTAs/SM =============
#define M3_AROWB 80
#define M3_SZ    (128*M3_AROWB)      // 10240
#define M3_STG   (2*M3_SZ)           // 20480
#define M3_STAGES 4
#define M3_SMEM  (M3_STAGES*M3_STG)  // 81920
#define M3_ITERS 32

__device__ __forceinline__ void m3_issue(uint32_t sbase, int stage, int it,
                                         int bm, int bn, int tid) {
    int kk = it << 5;
    uint32_t ab = sbase + stage * M3_STG;
    uint32_t bb = ab + M3_SZ;
    #pragma unroll
    for (int j = 0; j < 2; j++) {
        int id = tid + j * 256;
        int r = id >> 2, c = id & 3;
        cp16(ab + r * M3_AROWB + c * 16,
             g_Ah + (size_t)(bm + r) * E_ + kk + c * 8);
        cp16(bb + r * M3_AROWB + c * 16,
             g_Bh + (size_t)(bn + r) * E_ + kk + c * 8);
    }
}

__global__ void __launch_bounds__(256, 2) main_gemm_v3(const float* __restrict__ ob,
                                                       float* __restrict__ out) {
    extern __shared__ char smem[];
    uint32_t sbase = smem_u32(smem);
    int tid = threadIdx.x, wid = tid >> 5, lane = tid & 31;
    int bm = blockIdx.y * 128, bn = blockIdx.x * 128;
    int wm = wid & 1, wn = wid >> 1;   // warp tile: rows wm*64, cols wn*32

    float acc[4][4][4] = {};

    m3_issue(sbase, 0, 0, bm, bn, tid); CP_COMMIT();
    m3_issue(sbase, 1, 1, bm, bn, tid); CP_COMMIT();
    m3_issue(sbase, 2, 2, bm, bn, tid); CP_COMMIT();

    int l15 = lane & 15, l16 = lane >> 4;

    for (int i = 0; i < M3_ITERS; i++) {
        CP_WAIT2();
        __syncthreads();
        int s = i & 3;
        uint32_t ab = sbase + s * M3_STG;
        uint32_t bb = ab + M3_SZ;
        #pragma unroll
        for (int ks = 0; ks < 2; ks++) {
            int kc = ks * 2;
            uint32_t aaddr = ab + (wm * 64 + l15) * M3_AROWB + (kc + l16) * 16;
            uint32_t baddr = bb + (wn * 32 + l15) * M3_AROWB + (kc + l16) * 16;
            uint32_t ar[4][4], br[2][4];
            #pragma unroll
            for (int mi = 0; mi < 4; mi++)
                ldm4(ar[mi][0], ar[mi][1], ar[mi][2], ar[mi][3],
                     aaddr + mi * 16 * M3_AROWB);
            #pragma unroll
            for (int nb = 0; nb < 2; nb++)
                ldm4(br[nb][0], br[nb][1], br[nb][2], br[nb][3],
                     baddr + nb * 16 * M3_AROWB);
            #pragma unroll
            for (int mi = 0; mi < 4; mi++) {
                #pragma unroll
                for (int nb = 0; nb < 2; nb++) {
                    mma16816(acc[mi][2 * nb + 0], ar[mi], br[nb][0], br[nb][2]);
                    mma16816(acc[mi][2 * nb + 1], ar[mi], br[nb][1], br[nb][3]);
                }
            }
        }
        if (i + 3 < M3_ITERS)
            m3_issue(sbase, (i + 3) & 3, i + 3, bm, bn, tid);
        CP_COMMIT();
    }

    int lr = lane >> 2, lc = (lane & 3) * 2;
    #pragma unroll
    for (int mi = 0; mi < 4; mi++) {
        int row0 = bm + wm * 64 + mi * 16 + lr;
        int row1 = row0 + 8;
        float am0 = g_attn[row0], am1 = g_attn[row1];
        const float* vo0 = g_vo + (size_t)(row0 >> 6) * E_;
        const float* vo1 = g_vo + (size_t)(row1 >> 6) * E_;
        float* o0 = out + (size_t)row0 * E_;
        float* o1 = out + (size_t)row1 * E_;
        #pragma unroll
        for (int ni = 0; ni < 4; ni++) {
            int col = bn + wn * 32 + ni * 8 + lc;
            float2 r0, r1;
            r0.x = acc[mi][ni][0] + am0 * vo0[col]     + ob[col];
            r0.y = acc[mi][ni][1] + am0 * vo0[col + 1] + ob[col + 1];
            r1.x = acc[mi][ni][2] + am1 * vo1[col]     + ob[col];
            r1.y = acc[mi][ni][3] + am1 * vo1[col + 1] + ob[col + 1];
            *(float2*)(o0 + col) = r0;
            *(float2*)(o1 + col) = r1;
        }
    }
}

extern "C" void kernel_launch(void* const* d_in, const int* in_sizes, int n_in,
                              void* d_out, int out_size) {
    const float* re    = (const float*)d_in[0];
    const float* ctx   = (const float*)d_in[1];
    const float* qW    = (const float*)d_in[2];
    const float* qb    = (const float*)d_in[3];
    const float* kW    = (const float*)d_in[4];
    const float* kb    = (const float*)d_in[5];
    const float* vW    = (const float*)d_in[6];
    const float* vb    = (const float*)d_in[7];
    const float* oW    = (const float*)d_in[8];
    const float* ob    = (const float*)d_in[9];
    const float* lnq_g = (const float*)d_in[10];
    const float* lnq_b = (const float*)d_in[11];
    const float* lnk_g = (const float*)d_in[12];
    const float* lnk_b = (const float*)d_in[13];
    float* out = (float*)d_out;

    void *p_nkh, *p_kwh, *p_vwh, *p_qwth, *p_k, *p_kh, *p_vh, *p_w, *p_gw, *p_vo, *p_bh;
    cudaGetSymbolAddress(&p_nkh,  g_nk_h);
    cudaGetSymbolAddress(&p_kwh,  g_kWh);
    cudaGetSymbolAddress(&p_vwh,  g_vWh);
    cudaGetSymbolAddress(&p_qwth, g_qWTh);
    cudaGetSymbolAddress(&p_k,    g_k);
    cudaGetSymbolAddress(&p_kh,   g_k_h);
    cudaGetSymbolAddress(&p_vh,   g_v_h);
    cudaGetSymbolAddress(&p_w,    g_w);
    cudaGetSymbolAddress(&p_gw,   g_gw);
    cudaGetSymbolAddress(&p_vo,   g_vo);
    cudaGetSymbolAddress(&p_bh,   g_Bh);

    const int ag_smem = AG_STAGES * AG_STG;   // 61440
    cudaFuncSetAttribute(gemm_h_dual, cudaFuncAttributeMaxDynamicSharedMemorySize, ag_smem);
    cudaFuncSetAttribute(main_gemm_v3, cudaFuncAttributeMaxDynamicSharedMemorySize, M3_SMEM);

    // 0. prep: weight converts + qW transpose + LN(ctx)
    prep_kernel<<<4096, 256>>>(oW, kW, vW, qW, ctx, lnk_g, lnk_b,
                               (__half*)p_bh, (__half*)p_kwh, (__half*)p_vwh,
                               (__half*)p_qwth);
    // 1. k = nk@kW^T+kb  ||  v = nk@vW^T+vb
    {
        GemmArgs gk = { (__half*)p_nkh, (__half*)p_kwh, kb, (float*)p_k, (__half*)p_kh, nullptr, nullptr };
        GemmArgs gv = { (__half*)p_nkh, (__half*)p_vwh, vb, nullptr, (__half*)p_vh, nullptr, nullptr };
        gemm_h_dual<<<dim3(8, 8, 2), 256, ag_smem>>>(gk, gv, D_);
    }
    // 2. w = k@qW (+gw)  ||  vo = v@oW^T
    {
        GemmArgs gw_ = { (__half*)p_kh, (__half*)p_qwth, nullptr, (float*)p_w, nullptr, lnq_g, (float*)p_gw };
        GemmArgs gvo = { (__half*)p_vh, (__half*)p_bh, nullptr, (float*)p_vo, nullptr, nullptr, nullptr };
        gemm_h_dual<<<dim3(8, 8, 2), 256, ag_smem>>>(gw_, gvo, E_);
    }
    // 3. per-batch scalars (block per batch)
    scalars_kernel<<<B_, 256>>>(qb, lnq_b);
    // 4. attn per (b,n) row + re -> fp16 (fused)
    attn_cvt_kernel<<<M_ / 8, 256>>>(re);
    // 5. out = re @ oW^T + attn*vo + ob  (128x128, 4-stage, 2 CTAs/SM)
    main_gemm_v3<<<dim3(8, 512), 256, M3_SMEM>>>(ob, out);
}